// round 3
// baseline (speedup 1.0000x reference)
#include <cuda_runtime.h>
#include <cstdint>

// Problem constants (fixed for this problem instance)
#define BDIM 8192      // batch
#define DDIM 768       // model dim
#define FDIM 24576     // dict size
#define KTOP 64        // top-k
#define KSEL 96        // candidate pool for fp64 re-ranking

typedef unsigned long long ull;

// ---------------- device scratch (allocation-free rule: __device__ globals) ---
__device__ float g_post[(size_t)BDIM * FDIM];   // post-ReLU preactivations [B,F]
__device__ float g_cenc[FDIM];                  // b_enc[n] - dot(b_dec, W_enc[n,:])
__device__ float g_topv96[BDIM * KSEL];
__device__ int   g_topi96[BDIM * KSEL];
__device__ float g_topv[BDIM * KTOP];
__device__ int   g_topi[BDIM * KTOP];
__device__ float g_wdt[(size_t)FDIM * DDIM];    // W_dec transposed -> [F, D]

// ---------------- helpers ----------------------------------------------------
__device__ __forceinline__ void fma2(ull& d, ull a, ull b) {
    asm("fma.rn.f32x2 %0, %1, %2, %0;" : "+l"(d) : "l"(a), "l"(b));
}
__device__ __forceinline__ float2 asf2(ull v) {
    float2 r; asm("mov.b64 {%0, %1}, %2;" : "=f"(r.x), "=f"(r.y) : "l"(v));
    return r;
}

// ---------------- kernel 0: fold biases into per-feature constant -------------
__global__ void cenc_kernel(const float* __restrict__ W,
                            const float* __restrict__ be,
                            const float* __restrict__ bd) {
    int gw = (blockIdx.x * blockDim.x + threadIdx.x) >> 5;
    int lane = threadIdx.x & 31;
    if (gw >= FDIM) return;
    const float* wr = W + (size_t)gw * DDIM;
    float s = 0.f;
    for (int k = lane; k < DDIM; k += 32) s += bd[k] * wr[k];
    #pragma unroll
    for (int o = 16; o; o >>= 1) s += __shfl_xor_sync(0xffffffffu, s, o);
    if (lane == 0) g_cenc[gw] = be[gw] - s;
}

// ---------------- kernel 1: W_dec transpose [D,F] -> [F,D] -------------------
__global__ void transpose_kernel(const float* __restrict__ wd) {
    __shared__ float tile[32][33];
    int bx = blockIdx.x, by = blockIdx.y;
    int tx = threadIdx.x, ty = threadIdx.y;     // 32 x 8
    int f = bx * 32 + tx;
    #pragma unroll
    for (int j = 0; j < 32; j += 8)
        tile[ty + j][tx] = wd[(size_t)(by * 32 + ty + j) * FDIM + f];
    __syncthreads();
    int d = by * 32 + tx;
    #pragma unroll
    for (int j = 0; j < 32; j += 8)
        g_wdt[(size_t)(bx * 32 + ty + j) * DDIM + d] = tile[tx][ty + j];
}

// ---------------- kernel 2: encode GEMM + bias + ReLU ------------------------
// 128x128 tile, BK=8, 256 threads, packed f32x2 FMA, A duplicated in smem.
#define SA_STRIDE 260
#define SB_STRIDE 132

__global__ __launch_bounds__(256, 2)
void gemm_relu_kernel(const float* __restrict__ X, const float* __restrict__ W) {
    const int t  = threadIdx.x;
    const int tx = t & 15, ty = t >> 4;
    const int n0 = blockIdx.x * 128, m0 = blockIdx.y * 128;

    __shared__ __align__(16) float sA[8 * SA_STRIDE];
    __shared__ __align__(16) float sB[8 * SB_STRIDE];

    ull acc[8][4];
    #pragma unroll
    for (int i = 0; i < 8; i++)
        #pragma unroll
        for (int p = 0; p < 4; p++) acc[i][p] = 0ull;

    const int rr = t >> 1;
    const int lk = (t & 1) * 4;
    const float* ap = X + (size_t)(m0 + rr) * DDIM + lk;
    const float* bp = W + (size_t)(n0 + rr) * DDIM + lk;

    float4 ra = *(const float4*)ap;
    float4 rb = *(const float4*)bp;

    for (int kt = 0; kt < DDIM; kt += 8) {
        {
            const float va[4] = {ra.x, ra.y, ra.z, ra.w};
            const float vb[4] = {rb.x, rb.y, rb.z, rb.w};
            #pragma unroll
            for (int j = 0; j < 4; j++) {
                *(float2*)&sA[(lk + j) * SA_STRIDE + 2 * rr] = make_float2(va[j], va[j]);
                sB[(lk + j) * SB_STRIDE + rr] = vb[j];
            }
        }
        __syncthreads();

        const bool more = (kt + 8) < DDIM;
        if (more) {
            ra = *(const float4*)(ap + kt + 8);
            rb = *(const float4*)(bp + kt + 8);
        }

        #pragma unroll
        for (int kk = 0; kk < 8; kk++) {
            const ulonglong2 A0 = *(const ulonglong2*)&sA[kk * SA_STRIDE + 8 * ty];
            const ulonglong2 A1 = *(const ulonglong2*)&sA[kk * SA_STRIDE + 8 * ty + 4];
            const ulonglong2 A2 = *(const ulonglong2*)&sA[kk * SA_STRIDE + 128 + 8 * ty];
            const ulonglong2 A3 = *(const ulonglong2*)&sA[kk * SA_STRIDE + 128 + 8 * ty + 4];
            const ulonglong2 B0 = *(const ulonglong2*)&sB[kk * SB_STRIDE + 4 * tx];
            const ulonglong2 B1 = *(const ulonglong2*)&sB[kk * SB_STRIDE + 64 + 4 * tx];
            ull a[8] = {A0.x, A0.y, A1.x, A1.y, A2.x, A2.y, A3.x, A3.y};
            ull b[4] = {B0.x, B0.y, B1.x, B1.y};
            #pragma unroll
            for (int i = 0; i < 8; i++)
                #pragma unroll
                for (int p = 0; p < 4; p++)
                    fma2(acc[i][p], a[i], b[p]);
        }
        __syncthreads();
    }

    const float4 c0 = *(const float4*)(g_cenc + n0 + 4 * tx);
    const float4 c1 = *(const float4*)(g_cenc + n0 + 64 + 4 * tx);
    #pragma unroll
    for (int i = 0; i < 8; i++) {
        const int m = m0 + 4 * ty + (i & 3) + ((i >> 2) << 6);
        float* outp = g_post + (size_t)m * FDIM + n0 + 4 * tx;
        float2 p0 = asf2(acc[i][0]), p1 = asf2(acc[i][1]);
        float2 p2 = asf2(acc[i][2]), p3 = asf2(acc[i][3]);
        float4 o0 = make_float4(fmaxf(p0.x + c0.x, 0.f), fmaxf(p0.y + c0.y, 0.f),
                                fmaxf(p1.x + c0.z, 0.f), fmaxf(p1.y + c0.w, 0.f));
        float4 o1 = make_float4(fmaxf(p2.x + c1.x, 0.f), fmaxf(p2.y + c1.y, 0.f),
                                fmaxf(p3.x + c1.z, 0.f), fmaxf(p3.y + c1.w, 0.f));
        *(float4*)outp = o0;
        *(float4*)(outp + 64) = o1;
    }
}

// ---------------- kernel 3: per-row top-96 candidates (radix select) ---------
#define MAXEQ 256

__global__ void topk_kernel() {
    const int row = blockIdx.x;
    const float* __restrict__ p = g_post + (size_t)row * FDIM;
    const int t = threadIdx.x, lane = t & 31;

    __shared__ unsigned hist[2048];
    __shared__ unsigned chunk[256];
    __shared__ unsigned s_prefix;
    __shared__ int s_remk;
    __shared__ unsigned s_gt, s_eqc;
    __shared__ int eqidx[MAXEQ];

    if (t == 0) { s_prefix = 0u; s_remk = KSEL; s_gt = 0u; s_eqc = 0u; }
    __syncthreads();

    const int shifts[3] = {20, 10, 0};
    const int bitsv [3] = {11, 10, 10};

    for (int s = 0; s < 3; s++) {
        const int shift = shifts[s];
        const int nb = 1 << bitsv[s];
        for (int i = t; i < 2048; i += 256) hist[i] = 0u;
        __syncthreads();
        const unsigned pfx = s_prefix;
        const int hs = shift + bitsv[s];

        for (int i = t; i < FDIM; i += 256) {
            unsigned key = __float_as_uint(p[i]);
            if (key == 0x80000000u) key = 0u;
            const bool ok = (s == 0) || ((key >> hs) == pfx);
            const unsigned bin = ok ? ((key >> shift) & (nb - 1)) : 0xffffffffu;
            const unsigned m = __match_any_sync(0xffffffffu, bin);
            if (ok && lane == (__ffs(m) - 1)) atomicAdd(&hist[bin], __popc(m));
        }
        __syncthreads();

        const int nchunks = nb / 8;
        if (t < nchunks) {
            const int base = nb - 8 * (t + 1);
            unsigned cs = 0;
            #pragma unroll
            for (int j = 0; j < 8; j++) cs += hist[base + j];
            chunk[t] = cs;
        }
        __syncthreads();
        if (t == 0) {
            int remk = s_remk;
            unsigned cum = 0;
            int c = 0;
            for (; c < nchunks; c++) {
                if (cum + chunk[c] >= (unsigned)remk) break;
                cum += chunk[c];
            }
            int bin = nb - 8 * c - 1;
            for (;; bin--) {
                unsigned h = hist[bin];
                if (cum + h >= (unsigned)remk) break;
                cum += h;
            }
            s_remk = remk - (int)cum;
            s_prefix = (pfx << bitsv[s]) | (unsigned)bin;
        }
        __syncthreads();
    }

    const unsigned T = s_prefix;
    const int remk = s_remk;

    for (int i = t; i < FDIM; i += 256) {
        unsigned key = __float_as_uint(p[i]);
        if (key == 0x80000000u) key = 0u;
        if (key > T) {
            unsigned pos = atomicAdd(&s_gt, 1u);
            g_topv96[row * KSEL + pos] = __uint_as_float(key);
            g_topi96[row * KSEL + pos] = i;
        }
    }
    __syncthreads();
    const unsigned cgt = s_gt;     // == KSEL - remk
    for (int i = t; i < FDIM; i += 256) {
        unsigned key = __float_as_uint(p[i]);
        if (key == 0x80000000u) key = 0u;
        if (key == T) {
            unsigned e = atomicAdd(&s_eqc, 1u);
            if (e < MAXEQ) eqidx[e] = i;
        }
    }
    __syncthreads();
    const int cnt = (int)min(s_eqc, (unsigned)MAXEQ);
    if (t < cnt) {
        const int my = eqidx[t];
        int r = 0;
        for (int j = 0; j < cnt; j++) r += (eqidx[j] < my);
        if (r < remk) {
            g_topv96[row * KSEL + cgt + r] = __uint_as_float(T);
            g_topi96[row * KSEL + cgt + r] = my;
        }
    }
}

// ---------------- kernel 3b: fp64 re-rank of the 96 candidates ---------------
// Recompute the 96 candidate preactivations in fp64 (ground truth) and select
// the top-64 by fp64 value, ties -> lowest index. Output values stay fp32.
__global__ __launch_bounds__(256, 4)
void refine_kernel(const float* __restrict__ X, const float* __restrict__ W) {
    const int row = blockIdx.x;
    const int t = threadIdx.x, lane = t & 31, w = t >> 5;   // 8 warps

    __shared__ float sx[DDIM];
    __shared__ double s_val[KSEL];
    __shared__ int    s_idx[KSEL];

    for (int i = t; i < DDIM; i += 256) sx[i] = X[(size_t)row * DDIM + i];
    if (t < KSEL) s_idx[t] = g_topi96[row * KSEL + t];
    __syncthreads();

    for (int j = w; j < KSEL; j += 8) {
        const float* wr = W + (size_t)s_idx[j] * DDIM;
        double s = 0.0;
        for (int k = lane; k < DDIM; k += 32)
            s = fma((double)sx[k], (double)wr[k], s);
        #pragma unroll
        for (int o = 16; o; o >>= 1) s += __shfl_xor_sync(0xffffffffu, s, o);
        if (lane == 0) s_val[j] = s + (double)g_cenc[s_idx[j]];
    }
    __syncthreads();

    if (t < KSEL) {
        const double mv = s_val[t];
        const int    mi = s_idx[t];
        int r = 0;
        for (int j = 0; j < KSEL; j++) {
            const double v = s_val[j];
            r += (v > mv) || (v == mv && s_idx[j] < mi);
        }
        if (r < KTOP) {
            g_topv[row * KTOP + r] = g_topv96[row * KSEL + t];  // fp32 value
            g_topi[row * KTOP + r] = mi;
        }
    }
}

// ---------------- kernel 4: sparse decode ------------------------------------
__global__ void decode_kernel(const float* __restrict__ b_dec,
                              float* __restrict__ out) {
    const int row = blockIdx.x;
    const int t = threadIdx.x;
    __shared__ float sv0[KTOP];
    __shared__ int   si0[KTOP];
    __shared__ float sv[KTOP];
    __shared__ int   si[KTOP];
    if (t < KTOP) {
        sv0[t] = g_topv[row * KTOP + t];
        si0[t] = g_topi[row * KTOP + t];
    }
    __syncthreads();
    if (t < KTOP) {              // sort by index ascending (indices unique)
        const int my = si0[t];
        int r = 0;
        #pragma unroll 8
        for (int j = 0; j < KTOP; j++) r += (si0[j] < my);
        si[r] = my;
        sv[r] = sv0[t];
    }
    __syncthreads();
    float a0 = 0.f, a1 = 0.f, a2 = 0.f;
    #pragma unroll 4
    for (int k = 0; k < KTOP; k++) {
        const float v = sv[k];
        const float* wv = g_wdt + (size_t)si[k] * DDIM;
        a0 = fmaf(v, wv[t],       a0);
        a1 = fmaf(v, wv[t + 256], a1);
        a2 = fmaf(v, wv[t + 512], a2);
    }
    float* o = out + (size_t)row * DDIM;
    o[t]       = a0 + b_dec[t];
    o[t + 256] = a1 + b_dec[t + 256];
    o[t + 512] = a2 + b_dec[t + 512];
}

// ---------------- host entry --------------------------------------------------
extern "C" void kernel_launch(void* const* d_in, const int* in_sizes, int n_in,
                              void* d_out, int out_size) {
    const float* x     = (const float*)d_in[0];   // [B, D]
    const float* W_enc = (const float*)d_in[1];   // [F, D]
    const float* b_enc = (const float*)d_in[2];   // [F]
    const float* W_dec = (const float*)d_in[3];   // [D, F]
    const float* b_dec = (const float*)d_in[4];   // [D]
    float* out = (float*)d_out;                   // [B, D]

    cenc_kernel<<<FDIM * 32 / 256, 256>>>(W_enc, b_enc, b_dec);
    transpose_kernel<<<dim3(FDIM / 32, DDIM / 32), dim3(32, 8)>>>(W_dec);
    gemm_relu_kernel<<<dim3(FDIM / 128, BDIM / 128), 256>>>(x, W_enc);
    topk_kernel<<<BDIM, 256>>>();
    refine_kernel<<<BDIM, 256>>>(x, W_enc);
    decode_kernel<<<BDIM, 256>>>(b_dec, out);
}

// round 4
// speedup vs baseline: 1.4677x; 1.4677x over previous
#include <cuda_runtime.h>
#include <cstdint>

#define BDIM 8192      // batch
#define DDIM 768       // model dim
#define FDIM 24576     // dict size
#define KTOP 64        // top-k
#define KSEL 96        // candidate pool for fp64 re-ranking

// ---------------- device scratch ---------------------------------------------
__device__ float g_post[(size_t)BDIM * FDIM];   // post-ReLU preactivations [B,F]
__device__ float g_cenc[FDIM];                  // b_enc[n] - dot(b_dec, W_enc[n,:])
__device__ int   g_topi96[BDIM * KSEL];
__device__ float g_topv[BDIM * KTOP];
__device__ int   g_topi[BDIM * KTOP];
__device__ float g_wdt[(size_t)FDIM * DDIM];    // W_dec transposed -> [F, D]

// ---------------- kernel 0: fold biases into per-feature constant -------------
__global__ void cenc_kernel(const float* __restrict__ W,
                            const float* __restrict__ be,
                            const float* __restrict__ bd) {
    int gw = (blockIdx.x * blockDim.x + threadIdx.x) >> 5;
    int lane = threadIdx.x & 31;
    if (gw >= FDIM) return;
    const float* wr = W + (size_t)gw * DDIM;
    float s = 0.f;
    for (int k = lane; k < DDIM; k += 32) s += bd[k] * wr[k];
    #pragma unroll
    for (int o = 16; o; o >>= 1) s += __shfl_xor_sync(0xffffffffu, s, o);
    if (lane == 0) g_cenc[gw] = be[gw] - s;
}

// ---------------- kernel 1: W_dec transpose [D,F] -> [F,D] -------------------
__global__ void transpose_kernel(const float* __restrict__ wd) {
    __shared__ float tile[32][33];
    int bx = blockIdx.x, by = blockIdx.y;
    int tx = threadIdx.x, ty = threadIdx.y;     // 32 x 8
    int f = bx * 32 + tx;
    #pragma unroll
    for (int j = 0; j < 32; j += 8)
        tile[ty + j][tx] = wd[(size_t)(by * 32 + ty + j) * FDIM + f];
    __syncthreads();
    int d = by * 32 + tx;
    #pragma unroll
    for (int j = 0; j < 32; j += 8)
        g_wdt[(size_t)(bx * 32 + ty + j) * DDIM + d] = tile[tx][ty + j];
}

// ---------------- kernel 2: encode GEMM (TF32 tensor cores) + bias + ReLU ----
// post[m,n] = relu( X[m,:] . W[n,:] + cenc[n] ), computed in TF32 HMMA.
// Precision note: only used to FORM THE CANDIDATE POOL; refine_kernel
// recomputes candidates in fp64 and emits exact values. TF32 error (~2e-3)
// << rank64->rank96 order-stat gap (~0.13), so the true top-64 is contained.
#define BK    16
#define SAK   20           // smem row stride (floats): conflict-free for
                           // both ldmatrix (80B row stride) and B scalar loads
#define BUFF  (128 * SAK)  // floats per buffer

__device__ __forceinline__ void cp16(uint32_t dst, const float* src) {
    asm volatile("cp.async.cg.shared.global [%0], [%1], 16;\n"
                 :: "r"(dst), "l"(src) : "memory");
}
__device__ __forceinline__ void ldmx4(uint32_t* r, uint32_t addr) {
    asm volatile("ldmatrix.sync.aligned.m8n8.x4.shared.b16 {%0,%1,%2,%3}, [%4];\n"
                 : "=r"(r[0]), "=r"(r[1]), "=r"(r[2]), "=r"(r[3]) : "r"(addr));
}
__device__ __forceinline__ void mma_tf32(float* c, const uint32_t* a,
                                         uint32_t b0, uint32_t b1) {
    asm volatile("mma.sync.aligned.m16n8k8.row.col.f32.tf32.tf32.f32 "
                 "{%0,%1,%2,%3}, {%4,%5,%6,%7}, {%8,%9}, {%0,%1,%2,%3};\n"
                 : "+f"(c[0]), "+f"(c[1]), "+f"(c[2]), "+f"(c[3])
                 : "r"(a[0]), "r"(a[1]), "r"(a[2]), "r"(a[3]), "r"(b0), "r"(b1));
}

__global__ __launch_bounds__(256, 2)
void gemm_tf32_kernel(const float* __restrict__ X, const float* __restrict__ W) {
    __shared__ __align__(16) float sA[2][BUFF];
    __shared__ __align__(16) float sB[2][BUFF];

    const int t = threadIdx.x;
    const int L = t & 31, w = t >> 5;
    const int wm = w & 1, wn = w >> 1;         // warp tile: rows wm*64, cols wn*32
    const int m0 = blockIdx.y * 128, n0 = blockIdx.x * 128;

    // ---- staging addresses (per thread: one row-half, 2x 16B per matrix) ----
    const int srow = t >> 1, shalf = (t & 1) * 8;
    const uint32_t aBase = (uint32_t)__cvta_generic_to_shared(&sA[0][0]);
    const uint32_t bBase = (uint32_t)__cvta_generic_to_shared(&sB[0][0]);
    const uint32_t sOff = (uint32_t)(srow * SAK + shalf) * 4u;
    const float* aSrc = X + (size_t)(m0 + srow) * DDIM + shalf;
    const float* bSrc = W + (size_t)(n0 + srow) * DDIM + shalf;

    // ---- fragment addresses ----
    // A (ldmatrix.x4): lanes 0-7 -> rows r, 8-15 -> r+8, 16-23 -> r (col+4),
    // 24-31 -> r+8 (col+4); matches tf32 a0..a3 fragment layout exactly.
    const int aRow = wm * 64 + (L & 7) + ((L >> 3) & 1) * 8;
    const int aCol = ((L >> 4) & 1) * 4;
    const uint32_t aFragBase = aBase + (uint32_t)(aRow * SAK + aCol) * 4u;
    // B scalar: b0 = B[k = L&3][n = wn*32 + nt*8 + L>>2], b1 at k+4
    const int bN = wn * 32 + (L >> 2);
    const int bK = (L & 3);

    float acc[4][4][4];
    #pragma unroll
    for (int mt = 0; mt < 4; mt++)
        #pragma unroll
        for (int nt = 0; nt < 4; nt++)
            #pragma unroll
            for (int r = 0; r < 4; r++) acc[mt][nt][r] = 0.f;

    // ---- prologue: stage tile 0 ----
    cp16(aBase + sOff,       aSrc);
    cp16(aBase + sOff + 16u, aSrc + 4);
    cp16(bBase + sOff,       bSrc);
    cp16(bBase + sOff + 16u, bSrc + 4);
    asm volatile("cp.async.commit_group;\n" ::: "memory");

    const int NIT = DDIM / BK;   // 48
    for (int it = 0; it < NIT; ++it) {
        const int buf = it & 1;
        if (it + 1 < NIT) {
            const uint32_t bo = (uint32_t)((buf ^ 1) * BUFF) * 4u + sOff;
            const int kt = (it + 1) * BK;
            cp16(aBase + bo,       aSrc + kt);
            cp16(aBase + bo + 16u, aSrc + kt + 4);
            cp16(bBase + bo,       bSrc + kt);
            cp16(bBase + bo + 16u, bSrc + kt + 4);
            asm volatile("cp.async.commit_group;\n" ::: "memory");
            asm volatile("cp.async.wait_group 1;\n" ::: "memory");
        } else {
            asm volatile("cp.async.wait_group 0;\n" ::: "memory");
        }
        __syncthreads();

        const uint32_t aB = aFragBase + (uint32_t)(buf * BUFF) * 4u;
        const float* bS = &sB[buf][(size_t)bN * SAK + bK];
        #pragma unroll
        for (int k8 = 0; k8 < 2; k8++) {
            uint32_t a[4][4];
            #pragma unroll
            for (int mt = 0; mt < 4; mt++)
                ldmx4(a[mt], aB + (uint32_t)(mt * 16 * SAK + k8 * 8) * 4u);
            uint32_t b0[4], b1[4];
            #pragma unroll
            for (int nt = 0; nt < 4; nt++) {
                const float* bp = bS + nt * 8 * SAK + k8 * 8;
                b0[nt] = __float_as_uint(bp[0]);
                b1[nt] = __float_as_uint(bp[4]);
            }
            #pragma unroll
            for (int mt = 0; mt < 4; mt++)
                #pragma unroll
                for (int nt = 0; nt < 4; nt++)
                    mma_tf32(acc[mt][nt], a[mt], b0[nt], b1[nt]);
        }
        __syncthreads();
    }

    // ---- epilogue: + cenc, ReLU, store float2 ----
    const int g = L >> 2, tig = L & 3;
    #pragma unroll
    for (int nt = 0; nt < 4; nt++) {
        const int n = n0 + wn * 32 + nt * 8 + 2 * tig;
        const float2 ce = *(const float2*)&g_cenc[n];
        #pragma unroll
        for (int mt = 0; mt < 4; mt++) {
            const int m = m0 + wm * 64 + mt * 16 + g;
            float2 v0 = make_float2(fmaxf(acc[mt][nt][0] + ce.x, 0.f),
                                    fmaxf(acc[mt][nt][1] + ce.y, 0.f));
            float2 v1 = make_float2(fmaxf(acc[mt][nt][2] + ce.x, 0.f),
                                    fmaxf(acc[mt][nt][3] + ce.y, 0.f));
            *(float2*)&g_post[(size_t)m * FDIM + n]       = v0;
            *(float2*)&g_post[(size_t)(m + 8) * FDIM + n] = v1;
        }
    }
}

// ---------------- kernel 3: per-row top-96 candidates (radix select) ---------
#define MAXEQ 256

__global__ void topk_kernel() {
    const int row = blockIdx.x;
    const float* __restrict__ p = g_post + (size_t)row * FDIM;
    const int t = threadIdx.x, lane = t & 31;

    __shared__ unsigned hist[2048];
    __shared__ unsigned chunk[256];
    __shared__ unsigned s_prefix;
    __shared__ int s_remk;
    __shared__ unsigned s_gt, s_eqc;
    __shared__ int eqidx[MAXEQ];

    if (t == 0) { s_prefix = 0u; s_remk = KSEL; s_gt = 0u; s_eqc = 0u; }
    __syncthreads();

    const int shifts[3] = {20, 10, 0};
    const int bitsv [3] = {11, 10, 10};

    for (int s = 0; s < 3; s++) {
        const int shift = shifts[s];
        const int nb = 1 << bitsv[s];
        for (int i = t; i < 2048; i += 256) hist[i] = 0u;
        __syncthreads();
        const unsigned pfx = s_prefix;
        const int hs = shift + bitsv[s];

        for (int i = t; i < FDIM; i += 256) {
            unsigned key = __float_as_uint(p[i]);
            if (key == 0x80000000u) key = 0u;
            const bool ok = (s == 0) || ((key >> hs) == pfx);
            const unsigned bin = ok ? ((key >> shift) & (nb - 1)) : 0xffffffffu;
            const unsigned m = __match_any_sync(0xffffffffu, bin);
            if (ok && lane == (__ffs(m) - 1)) atomicAdd(&hist[bin], __popc(m));
        }
        __syncthreads();

        const int nchunks = nb / 8;
        if (t < nchunks) {
            const int base = nb - 8 * (t + 1);
            unsigned cs = 0;
            #pragma unroll
            for (int j = 0; j < 8; j++) cs += hist[base + j];
            chunk[t] = cs;
        }
        __syncthreads();
        if (t == 0) {
            int remk = s_remk;
            unsigned cum = 0;
            int c = 0;
            for (; c < nchunks; c++) {
                if (cum + chunk[c] >= (unsigned)remk) break;
                cum += chunk[c];
            }
            int bin = nb - 8 * c - 1;
            for (;; bin--) {
                unsigned h = hist[bin];
                if (cum + h >= (unsigned)remk) break;
                cum += h;
            }
            s_remk = remk - (int)cum;
            s_prefix = (pfx << bitsv[s]) | (unsigned)bin;
        }
        __syncthreads();
    }

    const unsigned T = s_prefix;
    const int remk = s_remk;

    for (int i = t; i < FDIM; i += 256) {
        unsigned key = __float_as_uint(p[i]);
        if (key == 0x80000000u) key = 0u;
        if (key > T) {
            unsigned pos = atomicAdd(&s_gt, 1u);
            g_topi96[row * KSEL + pos] = i;
        }
    }
    __syncthreads();
    const unsigned cgt = s_gt;     // == KSEL - remk
    for (int i = t; i < FDIM; i += 256) {
        unsigned key = __float_as_uint(p[i]);
        if (key == 0x80000000u) key = 0u;
        if (key == T) {
            unsigned e = atomicAdd(&s_eqc, 1u);
            if (e < MAXEQ) eqidx[e] = i;
        }
    }
    __syncthreads();
    const int cnt = (int)min(s_eqc, (unsigned)MAXEQ);
    if (t < cnt) {
        const int my = eqidx[t];
        int r = 0;
        for (int j = 0; j < cnt; j++) r += (eqidx[j] < my);
        if (r < remk) g_topi96[row * KSEL + cgt + r] = my;
    }
}

// ---------------- kernel 3b: fp64 re-rank of the 96 candidates ---------------
// Ground-truth values AND ground-truth selection; ties -> lowest index.
__global__ __launch_bounds__(256, 4)
void refine_kernel(const float* __restrict__ X, const float* __restrict__ W) {
    const int row = blockIdx.x;
    const int t = threadIdx.x, lane = t & 31, w = t >> 5;   // 8 warps

    __shared__ float sx[DDIM];
    __shared__ double s_val[KSEL];
    __shared__ int    s_idx[KSEL];

    for (int i = t; i < DDIM; i += 256) sx[i] = X[(size_t)row * DDIM + i];
    if (t < KSEL) s_idx[t] = g_topi96[row * KSEL + t];
    __syncthreads();

    for (int j = w; j < KSEL; j += 8) {
        const float* wr = W + (size_t)s_idx[j] * DDIM;
        double s = 0.0;
        for (int k = lane; k < DDIM; k += 32)
            s = fma((double)sx[k], (double)wr[k], s);
        #pragma unroll
        for (int o = 16; o; o >>= 1) s += __shfl_xor_sync(0xffffffffu, s, o);
        if (lane == 0) s_val[j] = s + (double)g_cenc[s_idx[j]];
    }
    __syncthreads();

    if (t < KSEL) {
        const double mv = s_val[t];
        const int    mi = s_idx[t];
        int r = 0;
        for (int j = 0; j < KSEL; j++) {
            const double v = s_val[j];
            r += (v > mv) || (v == mv && s_idx[j] < mi);
        }
        if (r < KTOP) {
            g_topv[row * KTOP + r] = (float)mv;   // fp64-accurate value
            g_topi[row * KTOP + r] = mi;
        }
    }
}

// ---------------- kernel 4: sparse decode ------------------------------------
__global__ void decode_kernel(const float* __restrict__ b_dec,
                              float* __restrict__ out) {
    const int row = blockIdx.x;
    const int t = threadIdx.x;
    __shared__ float sv0[KTOP];
    __shared__ int   si0[KTOP];
    __shared__ float sv[KTOP];
    __shared__ int   si[KTOP];
    if (t < KTOP) {
        sv0[t] = g_topv[row * KTOP + t];
        si0[t] = g_topi[row * KTOP + t];
    }
    __syncthreads();
    if (t < KTOP) {              // sort by index ascending (indices unique)
        const int my = si0[t];
        int r = 0;
        #pragma unroll 8
        for (int j = 0; j < KTOP; j++) r += (si0[j] < my);
        si[r] = my;
        sv[r] = sv0[t];
    }
    __syncthreads();
    float a0 = 0.f, a1 = 0.f, a2 = 0.f;
    #pragma unroll 4
    for (int k = 0; k < KTOP; k++) {
        const float v = sv[k];
        const float* wv = g_wdt + (size_t)si[k] * DDIM;
        a0 = fmaf(v, wv[t],       a0);
        a1 = fmaf(v, wv[t + 256], a1);
        a2 = fmaf(v, wv[t + 512], a2);
    }
    float* o = out + (size_t)row * DDIM;
    o[t]       = a0 + b_dec[t];
    o[t + 256] = a1 + b_dec[t + 256];
    o[t + 512] = a2 + b_dec[t + 512];
}

// ---------------- host entry --------------------------------------------------
extern "C" void kernel_launch(void* const* d_in, const int* in_sizes, int n_in,
                              void* d_out, int out_size) {
    const float* x     = (const float*)d_in[0];   // [B, D]
    const float* W_enc = (const float*)d_in[1];   // [F, D]
    const float* b_enc = (const float*)d_in[2];   // [F]
    const float* W_dec = (const float*)d_in[3];   // [D, F]
    const float* b_dec = (const float*)d_in[4];   // [D]
    float* out = (float*)d_out;                   // [B, D]

    cenc_kernel<<<FDIM * 32 / 256, 256>>>(W_enc, b_enc, b_dec);
    transpose_kernel<<<dim3(FDIM / 32, DDIM / 32), dim3(32, 8)>>>(W_dec);
    gemm_tf32_kernel<<<dim3(FDIM / 128, BDIM / 128), 256>>>(x, W_enc);
    topk_kernel<<<BDIM, 256>>>();
    refine_kernel<<<BDIM, 256>>>(x, W_enc);
    decode_kernel<<<BDIM, 256>>>(b_dec, out);
}

// round 11
// speedup vs baseline: 1.9174x; 1.3064x over previous
#include <cuda_runtime.h>
#include <cuda_bf16.h>
#include <cstdint>

#define BDIM 8192      // batch
#define DDIM 768       // model dim
#define FDIM 24576     // dict size
#define KTOP 64        // top-k
#define KSEL 96        // candidate pool for fp64 re-ranking

// ---------------- device scratch ---------------------------------------------
__device__ float g_post[(size_t)BDIM * FDIM];   // post-ReLU preacts [B,F]
__device__ float g_cenc[FDIM];                  // b_enc[n] - dot(b_dec, W_enc[n,:])
__device__ int   g_topi96[BDIM * KSEL];
__device__ float g_topv[BDIM * KTOP];
__device__ int   g_topi[BDIM * KTOP];
__device__ float g_wdt[(size_t)FDIM * DDIM];    // W_dec transposed -> [F, D]
__device__ __nv_bfloat16 g_xb[(size_t)BDIM * DDIM];  // X in bf16
__device__ __nv_bfloat16 g_wb[(size_t)FDIM * DDIM];  // W_enc in bf16

// ---------------- kernel 0: fold biases --------------------------------------
__global__ void cenc_kernel(const float* __restrict__ W,
                            const float* __restrict__ be,
                            const float* __restrict__ bd) {
    int gw = (blockIdx.x * blockDim.x + threadIdx.x) >> 5;
    int lane = threadIdx.x & 31;
    if (gw >= FDIM) return;
    const float* wr = W + (size_t)gw * DDIM;
    float s = 0.f;
    for (int k = lane; k < DDIM; k += 32) s += bd[k] * wr[k];
    #pragma unroll
    for (int o = 16; o; o >>= 1) s += __shfl_xor_sync(0xffffffffu, s, o);
    if (lane == 0) g_cenc[gw] = be[gw] - s;
}

// ---------------- bf16 conversion kernels ------------------------------------
__global__ void cvt_x_kernel(const float* __restrict__ s) {
    size_t i = ((size_t)blockIdx.x * 256 + threadIdx.x) * 4;
    float4 v = *(const float4*)(s + i);
    *(__nv_bfloat162*)(g_xb + i)     = __floats2bfloat162_rn(v.x, v.y);
    *(__nv_bfloat162*)(g_xb + i + 2) = __floats2bfloat162_rn(v.z, v.w);
}
__global__ void cvt_w_kernel(const float* __restrict__ s) {
    size_t i = ((size_t)blockIdx.x * 256 + threadIdx.x) * 4;
    float4 v = *(const float4*)(s + i);
    *(__nv_bfloat162*)(g_wb + i)     = __floats2bfloat162_rn(v.x, v.y);
    *(__nv_bfloat162*)(g_wb + i + 2) = __floats2bfloat162_rn(v.z, v.w);
}

// ---------------- kernel 1: W_dec transpose [D,F] -> [F,D] -------------------
__global__ void transpose_kernel(const float* __restrict__ wd) {
    __shared__ float tile[32][33];
    int bx = blockIdx.x, by = blockIdx.y;
    int tx = threadIdx.x, ty = threadIdx.y;     // 32 x 8
    int f = bx * 32 + tx;
    #pragma unroll
    for (int j = 0; j < 32; j += 8)
        tile[ty + j][tx] = wd[(size_t)(by * 32 + ty + j) * FDIM + f];
    __syncthreads();
    int d = by * 32 + tx;
    #pragma unroll
    for (int j = 0; j < 32; j += 8)
        g_wdt[(size_t)(bx * 32 + ty + j) * DDIM + d] = tile[tx][ty + j];
}

// ---------------- kernel 2: encode GEMM (bf16 mma.sync m16n8k16) -------------
// post[m,n] = relu( X[m,:] . W[n,:] + cenc[n] ); bf16 inputs, fp32 accum.
// Candidate-pool precision only; refine_kernel provides exact values/selection.
#define BK   32                 // K per tile (bf16)
#define STR  40                 // smem row stride in bf16 (80B, conflict-free)
#define TILEE (128 * STR)       // bf16 elements per buffer

__device__ __forceinline__ void cp16(uint32_t dst, const void* src) {
    asm volatile("cp.async.cg.shared.global [%0], [%1], 16;\n"
                 :: "r"(dst), "l"(src) : "memory");
}
__device__ __forceinline__ void ldmx4(uint32_t* r, uint32_t addr) {
    asm volatile("ldmatrix.sync.aligned.m8n8.x4.shared.b16 {%0,%1,%2,%3}, [%4];\n"
                 : "=r"(r[0]), "=r"(r[1]), "=r"(r[2]), "=r"(r[3]) : "r"(addr));
}
__device__ __forceinline__ void mma_bf16(float* c, const uint32_t* a,
                                         uint32_t b0, uint32_t b1) {
    asm volatile("mma.sync.aligned.m16n8k16.row.col.f32.bf16.bf16.f32 "
                 "{%0,%1,%2,%3}, {%4,%5,%6,%7}, {%8,%9}, {%0,%1,%2,%3};\n"
                 : "+f"(c[0]), "+f"(c[1]), "+f"(c[2]), "+f"(c[3])
                 : "r"(a[0]), "r"(a[1]), "r"(a[2]), "r"(a[3]), "r"(b0), "r"(b1));
}

__global__ __launch_bounds__(256, 2)
void gemm_bf16_kernel() {
    __shared__ __align__(16) __nv_bfloat16 sA[2][TILEE];
    __shared__ __align__(16) __nv_bfloat16 sB[2][TILEE];

    const int t = threadIdx.x;
    const int L = t & 31, w = t >> 5;
    const int wm = w & 1, wn = w >> 1;         // warp tile: rows wm*64, cols wn*32
    const int m0 = blockIdx.y * 128, n0 = blockIdx.x * 128;

    // ---- staging: thread t covers row (t>>1), 32B half (t&1) of each matrix --
    const int srow = t >> 1, soff = (t & 1) * 16;   // element offset in row
    const uint32_t aBase = (uint32_t)__cvta_generic_to_shared(&sA[0][0]);
    const uint32_t bBase = (uint32_t)__cvta_generic_to_shared(&sB[0][0]);
    const uint32_t sOff = (uint32_t)(srow * STR + soff) * 2u;
    const __nv_bfloat16* aSrc = g_xb + (size_t)(m0 + srow) * DDIM + soff;
    const __nv_bfloat16* bSrc = g_wb + (size_t)(n0 + srow) * DDIM + soff;

    // ---- fragment addresses ----
    // A via ldmatrix.x4.b16: lane -> row (L&15), col-half (L>>4)*8 bf16
    const int aRow = wm * 64 + (L & 15);
    const uint32_t aFragBase = aBase + (uint32_t)(aRow * STR + (L >> 4) * 8) * 2u;
    // B scalar bf162 loads: n = wn*32 + nt*8 + (L>>2), k pair at 2*(L&3)
    const int bN = wn * 32 + (L >> 2);
    const int bK = 2 * (L & 3);

    float acc[4][4][4];
    #pragma unroll
    for (int mt = 0; mt < 4; mt++)
        #pragma unroll
        for (int nt = 0; nt < 4; nt++)
            #pragma unroll
            for (int r = 0; r < 4; r++) acc[mt][nt][r] = 0.f;

    // ---- prologue: stage tile 0 ----
    cp16(aBase + sOff,       aSrc);
    cp16(aBase + sOff + 16u, aSrc + 8);
    cp16(bBase + sOff,       bSrc);
    cp16(bBase + sOff + 16u, bSrc + 8);
    asm volatile("cp.async.commit_group;\n" ::: "memory");

    const int NIT = DDIM / BK;   // 24
    for (int it = 0; it < NIT; ++it) {
        const int buf = it & 1;
        if (it + 1 < NIT) {
            const uint32_t bo = (uint32_t)((buf ^ 1) * TILEE) * 2u + sOff;
            const int kt = (it + 1) * BK;
            cp16(aBase + bo,       aSrc + kt);
            cp16(aBase + bo + 16u, aSrc + kt + 8);
            cp16(bBase + bo,       bSrc + kt);
            cp16(bBase + bo + 16u, bSrc + kt + 8);
            asm volatile("cp.async.commit_group;\n" ::: "memory");
            asm volatile("cp.async.wait_group 1;\n" ::: "memory");
        } else {
            asm volatile("cp.async.wait_group 0;\n" ::: "memory");
        }
        __syncthreads();

        const uint32_t aB = aFragBase + (uint32_t)(buf * TILEE) * 2u;
        const __nv_bfloat16* bS = &sB[buf][(size_t)bN * STR + bK];
        #pragma unroll
        for (int k16 = 0; k16 < 2; k16++) {
            uint32_t a[4][4];
            #pragma unroll
            for (int mt = 0; mt < 4; mt++)
                ldmx4(a[mt], aB + (uint32_t)(mt * 16 * STR + k16 * 16) * 2u);
            uint32_t b0[4], b1[4];
            #pragma unroll
            for (int nt = 0; nt < 4; nt++) {
                const __nv_bfloat16* bp = bS + nt * 8 * STR + k16 * 16;
                b0[nt] = *(const uint32_t*)bp;
                b1[nt] = *(const uint32_t*)(bp + 8);
            }
            #pragma unroll
            for (int mt = 0; mt < 4; mt++)
                #pragma unroll
                for (int nt = 0; nt < 4; nt++)
                    mma_bf16(acc[mt][nt], a[mt], b0[nt], b1[nt]);
        }
        __syncthreads();
    }

    // ---- epilogue: + cenc, ReLU, store float2 ----
    const int g = L >> 2, tig = L & 3;
    #pragma unroll
    for (int nt = 0; nt < 4; nt++) {
        const int n = n0 + wn * 32 + nt * 8 + 2 * tig;
        const float2 ce = *(const float2*)&g_cenc[n];
        #pragma unroll
        for (int mt = 0; mt < 4; mt++) {
            const int m = m0 + wm * 64 + mt * 16 + g;
            float2 v0 = make_float2(fmaxf(acc[mt][nt][0] + ce.x, 0.f),
                                    fmaxf(acc[mt][nt][1] + ce.y, 0.f));
            float2 v1 = make_float2(fmaxf(acc[mt][nt][2] + ce.x, 0.f),
                                    fmaxf(acc[mt][nt][3] + ce.y, 0.f));
            *(float2*)&g_post[(size_t)m * FDIM + n]       = v0;
            *(float2*)&g_post[(size_t)(m + 8) * FDIM + n] = v1;
        }
    }
}

// ---------------- kernel 3: per-row top-96 (2-scan histogram select) ---------
#define NCAND 1024

__global__ void topk_kernel() {
    const int row = blockIdx.x;
    const float* __restrict__ p = g_post + (size_t)row * FDIM;
    const int t = threadIdx.x, lane = t & 31;

    __shared__ unsigned hist[4096];
    __shared__ unsigned csum[256];
    __shared__ int s_tbin;
    __shared__ unsigned s_cnt;
    __shared__ unsigned skey[NCAND];
    __shared__ int      sidx[NCAND];

    if (t == 0) s_cnt = 0u;
    #pragma unroll
    for (int j = 0; j < 16; j++) hist[t + 256 * j] = 0u;
    __syncthreads();

    // pass 1: 4096-bin histogram of top-12 float bits (values >= 0)
    for (int i = t; i < FDIM; i += 256) {
        unsigned key = __float_as_uint(p[i]);
        if (key == 0x80000000u) key = 0u;
        const unsigned bin = key >> 20;
        const unsigned m = __match_any_sync(0xffffffffu, bin);
        if (lane == (__ffs(m) - 1)) atomicAdd(&hist[bin], __popc(m));
    }
    __syncthreads();

    // descending chunk sums, then serial threshold-bin search
    {
        const int base = 4096 - 16 * (t + 1);
        unsigned cs = 0;
        #pragma unroll
        for (int j = 0; j < 16; j++) cs += hist[base + j];
        csum[t] = cs;
    }
    __syncthreads();
    if (t == 0) {
        unsigned cum = 0;
        int c = 0;
        while (cum + csum[c] < KSEL) { cum += csum[c]; c++; }
        int bin = 4096 - 16 * c - 1;
        while (cum + hist[bin] < KSEL) { cum += hist[bin]; bin--; }
        s_tbin = bin;
    }
    __syncthreads();
    const unsigned tb = (unsigned)s_tbin;

    // pass 2: collect all candidates in bins >= tb
    for (int i = t; i < FDIM; i += 256) {
        unsigned key = __float_as_uint(p[i]);
        if (key == 0x80000000u) key = 0u;
        if ((key >> 20) >= tb) {
            unsigned pos = atomicAdd(&s_cnt, 1u);
            if (pos < NCAND) { skey[pos] = key; sidx[pos] = i; }
        }
    }
    __syncthreads();
    const int n = (int)min(s_cnt, (unsigned)NCAND);

    // rank (value desc, index asc) and emit top-96 indices
    for (int s = t; s < n; s += 256) {
        const unsigned k = skey[s];
        const int id = sidx[s];
        int r = 0;
        for (int j = 0; j < n; j++) {
            const unsigned kj = skey[j];
            r += (kj > k) || (kj == k && sidx[j] < id);
        }
        if (r < KSEL) g_topi96[row * KSEL + r] = id;
    }
}

// ---------------- kernel 3b: fp64 re-rank of the 96 candidates ---------------
__global__ __launch_bounds__(256, 4)
void refine_kernel(const float* __restrict__ X, const float* __restrict__ W) {
    const int row = blockIdx.x;
    const int t = threadIdx.x, lane = t & 31, w = t >> 5;   // 8 warps

    __shared__ float sx[DDIM];
    __shared__ double s_val[KSEL];
    __shared__ int    s_idx[KSEL];

    for (int i = t; i < DDIM; i += 256) sx[i] = X[(size_t)row * DDIM + i];
    if (t < KSEL) s_idx[t] = g_topi96[row * KSEL + t];
    __syncthreads();

    for (int j = w; j < KSEL; j += 8) {
        const float* wr = W + (size_t)s_idx[j] * DDIM;
        double s = 0.0;
        for (int k = lane; k < DDIM; k += 32)
            s = fma((double)sx[k], (double)wr[k], s);
        #pragma unroll
        for (int o = 16; o; o >>= 1) s += __shfl_xor_sync(0xffffffffu, s, o);
        if (lane == 0) s_val[j] = s + (double)g_cenc[s_idx[j]];
    }
    __syncthreads();

    if (t < KSEL) {
        const double mv = s_val[t];
        const int    mi = s_idx[t];
        int r = 0;
        for (int j = 0; j < KSEL; j++) {
            const double v = s_val[j];
            r += (v > mv) || (v == mv && s_idx[j] < mi);
        }
        if (r < KTOP) {
            g_topv[row * KTOP + r] = (float)mv;   // fp64-accurate value
            g_topi[row * KTOP + r] = mi;
        }
    }
}

// ---------------- kernel 4: sparse decode ------------------------------------
__global__ void decode_kernel(const float* __restrict__ b_dec,
                              float* __restrict__ out) {
    const int row = blockIdx.x;
    const int t = threadIdx.x;
    __shared__ float sv0[KTOP];
    __shared__ int   si0[KTOP];
    __shared__ float sv[KTOP];
    __shared__ int   si[KTOP];
    if (t < KTOP) {
        sv0[t] = g_topv[row * KTOP + t];
        si0[t] = g_topi[row * KTOP + t];
    }
    __syncthreads();
    if (t < KTOP) {              // sort by index ascending (indices unique)
        const int my = si0[t];
        int r = 0;
        #pragma unroll 8
        for (int j = 0; j < KTOP; j++) r += (si0[j] < my);
        si[r] = my;
        sv[r] = sv0[t];
    }
    __syncthreads();
    float a0 = 0.f, a1 = 0.f, a2 = 0.f;
    #pragma unroll 4
    for (int k = 0; k < KTOP; k++) {
        const float v = sv[k];
        const float* wv = g_wdt + (size_t)si[k] * DDIM;
        a0 = fmaf(v, wv[t],       a0);
        a1 = fmaf(v, wv[t + 256], a1);
        a2 = fmaf(v, wv[t + 512], a2);
    }
    float* o = out + (size_t)row * DDIM;
    o[t]       = a0 + b_dec[t];
    o[t + 256] = a1 + b_dec[t + 256];
    o[t + 512] = a2 + b_dec[t + 512];
}

// ---------------- host entry --------------------------------------------------
extern "C" void kernel_launch(void* const* d_in, const int* in_sizes, int n_in,
                              void* d_out, int out_size) {
    const float* x     = (const float*)d_in[0];   // [B, D]
    const float* W_enc = (const float*)d_in[1];   // [F, D]
    const float* b_enc = (const float*)d_in[2];   // [F]
    const float* W_dec = (const float*)d_in[3];   // [D, F]
    const float* b_dec = (const float*)d_in[4];   // [D]
    float* out = (float*)d_out;                   // [B, D]

    cenc_kernel<<<FDIM * 32 / 256, 256>>>(W_enc, b_enc, b_dec);
    cvt_x_kernel<<<(BDIM * DDIM) / 1024, 256>>>(x);
    cvt_w_kernel<<<(FDIM * DDIM) / 1024, 256>>>(W_enc);
    transpose_kernel<<<dim3(FDIM / 32, DDIM / 32), dim3(32, 8)>>>(W_dec);
    gemm_bf16_kernel<<<dim3(FDIM / 128, BDIM / 128), 256>>>();
    topk_kernel<<<BDIM, 256>>>();
    refine_kernel<<<BDIM, 256>>>(x, W_enc);
    decode_kernel<<<BDIM, 256>>>(b_dec, out);
}